// round 3
// baseline (speedup 1.0000x reference)
#include <cuda_runtime.h>
#include <math.h>
#include <stdint.h>

#define N_LEVELS 16
#define LOG2_HASHMAP_SIZE 19
#define HASH_MASK ((1u << LOG2_HASHMAP_SIZE) - 1u)
#define N_POINTS 1048576
#define PRIME_Y 2654435761u
#define PRIME_Z 805459861u
#define N_BINS 32768          // 32^3 spatial bins over [0,1]^3

struct Res16 { float r[16]; };

// Scratch (no cudaMalloc allowed): sorted points + orig index packed in .w
__device__ float4       g_xs4[N_POINTS];     // 16 MB
__device__ unsigned int g_hist[N_BINS];      // counts -> offsets -> cursors

__device__ __forceinline__ int bin_key(float px, float py, float pz) {
    int bx = (int)(px * 32.0f); bx = bx < 0 ? 0 : (bx > 31 ? 31 : bx);
    int by = (int)(py * 32.0f); by = by < 0 ? 0 : (by > 31 ? 31 : by);
    int bz = (int)(pz * 32.0f); bz = bz < 0 ? 0 : (bz > 31 ? 31 : bz);
    return (bx << 10) | (by << 5) | bz;
}

__global__ void zero_hist_kernel() {
    int i = blockIdx.x * blockDim.x + threadIdx.x;
    if (i < N_BINS) g_hist[i] = 0u;
}

__global__ void hist_kernel(const float* __restrict__ x) {
    int i = blockIdx.x * blockDim.x + threadIdx.x;
    if (i >= N_POINTS) return;
    float px = __ldg(&x[3 * i]), py = __ldg(&x[3 * i + 1]), pz = __ldg(&x[3 * i + 2]);
    atomicAdd(&g_hist[bin_key(px, py, pz)], 1u);
}

// Single-block exclusive scan over 32768 bins (1024 threads x 32 bins each).
__global__ void scan_kernel() {
    __shared__ unsigned int s[1024];
    int t = threadIdx.x;
    unsigned int local[32];
    unsigned int sum = 0;
#pragma unroll
    for (int i = 0; i < 32; i++) { local[i] = g_hist[t * 32 + i]; sum += local[i]; }
    s[t] = sum;
    __syncthreads();
    for (int off = 1; off < 1024; off <<= 1) {
        unsigned int v = (t >= off) ? s[t - off] : 0u;
        __syncthreads();
        s[t] += v;
        __syncthreads();
    }
    unsigned int run = (t == 0) ? 0u : s[t - 1];
#pragma unroll
    for (int i = 0; i < 32; i++) { g_hist[t * 32 + i] = run; run += local[i]; }
}

__global__ void scatter_kernel(const float* __restrict__ x) {
    int i = blockIdx.x * blockDim.x + threadIdx.x;
    if (i >= N_POINTS) return;
    float px = __ldg(&x[3 * i]), py = __ldg(&x[3 * i + 1]), pz = __ldg(&x[3 * i + 2]);
    unsigned int r = atomicAdd(&g_hist[bin_key(px, py, pz)], 1u);
    g_xs4[r] = make_float4(px, py, pz, __int_as_float(i));
}

__device__ __forceinline__ float2 ldg_na(const float2* p) {
    float2 v;
    asm("ld.global.nc.L1::no_allocate.v2.f32 {%0, %1}, [%2];"
        : "=f"(v.x), "=f"(v.y) : "l"(p));
    return v;
}

__device__ __forceinline__ void st_cs(float2* p, float2 v) {
    asm volatile("st.global.cs.v2.f32 [%0], {%1, %2};"
                 :: "l"(p), "f"(v.x), "f"(v.y) : "memory");
}

// Main: block = 512 threads = 16 warps. Warp w handles level w for 32
// spatially-adjacent (sorted) points -> coarse-level gathers coalesce.
__global__ void __launch_bounds__(512)
hash_embed_kernel(const float* __restrict__ tables,
                  float2* __restrict__ out,
                  Res16 R)
{
    __shared__ float2 s_out[32][17];   // [point][level], padded row
    __shared__ int    s_idx[32];

    const int warp = threadIdx.x >> 5;   // = level
    const int lane = threadIdx.x & 31;   // = point within block
    const int base = blockIdx.x * 32;

    const float4 pv = __ldcs(&g_xs4[base + lane]);   // read-once: evict-first
    const float px = pv.x, py = pv.y, pz = pv.z;
    if (warp == 0) s_idx[lane] = __float_as_int(pv.w);

    const int level = warp;
    const float res  = R.r[level];
    const float grid = 2.0f / res;   // fp32, matches reference

    // bl = floor((x - BOX_MIN)/grid), BOX_MIN = -1. Bit-exact IEEE path.
    const float fx = (px + 1.0f) / grid;
    const float fy = (py + 1.0f) / grid;
    const float fz = (pz + 1.0f) / grid;
    const float bxf = floorf(fx);
    const float byf = floorf(fy);
    const float bzf = floorf(fz);
    const int bx = (int)bxf;
    const int by = (int)byf;
    const int bz = (int)bzf;

    // Weights: mathematically (x - vmin)/(vmax - vmin) == frac(fx); ~1 ulp
    // from the reference's formulation, far under the 1e-3 tolerance.
    const float wx = fx - bxf;
    const float wy = fy - byf;
    const float wz = fz - bzf;

    const uint32_t hx0 = (uint32_t)bx;
    const uint32_t hx1 = (uint32_t)(bx + 1);
    const uint32_t hy0 = (uint32_t)by * PRIME_Y;
    const uint32_t hy1 = (uint32_t)(by + 1) * PRIME_Y;
    const uint32_t hz0 = (uint32_t)bz * PRIME_Z;
    const uint32_t hz1 = (uint32_t)(bz + 1) * PRIME_Z;

    const float2* __restrict__ tab =
        (const float2*)tables + ((size_t)level << LOG2_HASHMAP_SIZE);

    float2 v000, v001, v010, v011, v100, v101, v110, v111;
    if (level >= 11) {
        // Finest tables (4MB each): ~0% L1 hit rate; don't allocate in L1,
        // preserve it for the mid/coarse levels that do hit.
        v000 = ldg_na(&tab[(hx0 ^ hy0 ^ hz0) & HASH_MASK]);
        v001 = ldg_na(&tab[(hx0 ^ hy0 ^ hz1) & HASH_MASK]);
        v010 = ldg_na(&tab[(hx0 ^ hy1 ^ hz0) & HASH_MASK]);
        v011 = ldg_na(&tab[(hx0 ^ hy1 ^ hz1) & HASH_MASK]);
        v100 = ldg_na(&tab[(hx1 ^ hy0 ^ hz0) & HASH_MASK]);
        v101 = ldg_na(&tab[(hx1 ^ hy0 ^ hz1) & HASH_MASK]);
        v110 = ldg_na(&tab[(hx1 ^ hy1 ^ hz0) & HASH_MASK]);
        v111 = ldg_na(&tab[(hx1 ^ hy1 ^ hz1) & HASH_MASK]);
    } else {
        v000 = __ldg(&tab[(hx0 ^ hy0 ^ hz0) & HASH_MASK]);
        v001 = __ldg(&tab[(hx0 ^ hy0 ^ hz1) & HASH_MASK]);
        v010 = __ldg(&tab[(hx0 ^ hy1 ^ hz0) & HASH_MASK]);
        v011 = __ldg(&tab[(hx0 ^ hy1 ^ hz1) & HASH_MASK]);
        v100 = __ldg(&tab[(hx1 ^ hy0 ^ hz0) & HASH_MASK]);
        v101 = __ldg(&tab[(hx1 ^ hy0 ^ hz1) & HASH_MASK]);
        v110 = __ldg(&tab[(hx1 ^ hy1 ^ hz0) & HASH_MASK]);
        v111 = __ldg(&tab[(hx1 ^ hy1 ^ hz1) & HASH_MASK]);
    }

    const float owx = 1.0f - wx;
    const float owy = 1.0f - wy;
    const float owz = 1.0f - wz;

    float2 c00, c01, c10, c11;
    c00.x = v000.x * owx + v100.x * wx;  c00.y = v000.y * owx + v100.y * wx;
    c01.x = v001.x * owx + v101.x * wx;  c01.y = v001.y * owx + v101.y * wx;
    c10.x = v010.x * owx + v110.x * wx;  c10.y = v010.y * owx + v110.y * wx;
    c11.x = v011.x * owx + v111.x * wx;  c11.y = v011.y * owx + v111.y * wx;

    float2 c0, c1;
    c0.x = c00.x * owy + c10.x * wy;  c0.y = c00.y * owy + c10.y * wy;
    c1.x = c01.x * owy + c11.x * wy;  c1.y = c01.y * owy + c11.y * wy;

    float2 r2;
    r2.x = c0.x * owz + c1.x * wz;
    r2.y = c0.y * owz + c1.y * wz;

    s_out[lane][warp] = r2;
    __syncthreads();

    // Coalesced writeback: 16 consecutive threads emit one point's 128B row.
    // Streaming store: output is write-once, keep it out of L2's way.
    const int pt  = threadIdx.x >> 4;
    const int lev = threadIdx.x & 15;
    st_cs(&out[(size_t)s_idx[pt] * N_LEVELS + lev], s_out[pt][lev]);
}

extern "C" void kernel_launch(void* const* d_in, const int* in_sizes, int n_in,
                              void* d_out, int out_size)
{
    const float* x      = (const float*)d_in[0];
    const float* tables = (const float*)d_in[1];
    float2* out         = (float2*)d_out;

    // Replicate numpy's RESOLUTIONS computation exactly (double libm, floor).
    Res16 R;
    const double b = exp((log(512.0) - log(16.0)) / 15.0);
    for (int i = 0; i < 16; i++) {
        R.r[i] = (float)floor(16.0 * pow(b, (double)i));
    }

    zero_hist_kernel<<<N_BINS / 1024, 1024>>>();
    hist_kernel<<<N_POINTS / 256, 256>>>(x);
    scan_kernel<<<1, 1024>>>();
    scatter_kernel<<<N_POINTS / 256, 256>>>(x);
    hash_embed_kernel<<<N_POINTS / 32, 512>>>(tables, out, R);
}

// round 4
// speedup vs baseline: 1.0932x; 1.0932x over previous
#include <cuda_runtime.h>
#include <math.h>
#include <stdint.h>

#define N_LEVELS 16
#define LOG2_HASHMAP_SIZE 19
#define HASH_MASK ((1u << LOG2_HASHMAP_SIZE) - 1u)
#define N_POINTS 1048576
#define PRIME_Y 2654435761u
#define PRIME_Z 805459861u
#define N_BINS 32768          // 32^3 spatial bins over [0,1]^3

struct Res16 { float r[16]; };

// Scratch (no cudaMalloc allowed): sorted points + orig index packed in .w
__device__ float4       g_xs4[N_POINTS];     // 16 MB
__device__ unsigned int g_hist[N_BINS];      // counts -> offsets -> cursors

__device__ __forceinline__ int bin_key(float px, float py, float pz) {
    int bx = (int)(px * 32.0f); bx = bx < 0 ? 0 : (bx > 31 ? 31 : bx);
    int by = (int)(py * 32.0f); by = by < 0 ? 0 : (by > 31 ? 31 : by);
    int bz = (int)(pz * 32.0f); bz = bz < 0 ? 0 : (bz > 31 ? 31 : bz);
    return (bx << 10) | (by << 5) | bz;
}

__global__ void zero_hist_kernel() {
    int i = blockIdx.x * blockDim.x + threadIdx.x;
    if (i < N_BINS) g_hist[i] = 0u;
}

__global__ void hist_kernel(const float* __restrict__ x) {
    int i = blockIdx.x * blockDim.x + threadIdx.x;
    if (i >= N_POINTS) return;
    float px = __ldg(&x[3 * i]), py = __ldg(&x[3 * i + 1]), pz = __ldg(&x[3 * i + 2]);
    atomicAdd(&g_hist[bin_key(px, py, pz)], 1u);
}

// Single-block exclusive scan over 32768 bins (1024 threads x 32 bins each).
__global__ void scan_kernel() {
    __shared__ unsigned int s[1024];
    int t = threadIdx.x;
    unsigned int local[32];
    unsigned int sum = 0;
#pragma unroll
    for (int i = 0; i < 32; i++) { local[i] = g_hist[t * 32 + i]; sum += local[i]; }
    s[t] = sum;
    __syncthreads();
    for (int off = 1; off < 1024; off <<= 1) {
        unsigned int v = (t >= off) ? s[t - off] : 0u;
        __syncthreads();
        s[t] += v;
        __syncthreads();
    }
    unsigned int run = (t == 0) ? 0u : s[t - 1];
#pragma unroll
    for (int i = 0; i < 32; i++) { g_hist[t * 32 + i] = run; run += local[i]; }
}

__global__ void scatter_kernel(const float* __restrict__ x) {
    int i = blockIdx.x * blockDim.x + threadIdx.x;
    if (i >= N_POINTS) return;
    float px = __ldg(&x[3 * i]), py = __ldg(&x[3 * i + 1]), pz = __ldg(&x[3 * i + 2]);
    unsigned int r = atomicAdd(&g_hist[bin_key(px, py, pz)], 1u);
    g_xs4[r] = make_float4(px, py, pz, __int_as_float(i));
}

// Load both x-corners (bx, bx+1) for a fixed (y,z) hash component.
// PRIME_X == 1, so when bx is even the two hashed indices are {2k, 2k+1}:
// a single aligned float4 covers both. Odd bx falls back to two float2 loads.
__device__ __forceinline__ void load_xpair(const float2* __restrict__ tab,
                                           int bx, uint32_t hyz,
                                           float2& v0, float2& v1)
{
    const uint32_t h0 = ((uint32_t)bx ^ hyz) & HASH_MASK;
    if ((bx & 1) == 0) {
        const float4 q = __ldg((const float4*)tab + (h0 >> 1));
        const float2 lo = make_float2(q.x, q.y);
        const float2 hi = make_float2(q.z, q.w);
        const bool odd = (h0 & 1u) != 0u;   // h1 = h0 ^ 1
        v0 = odd ? hi : lo;
        v1 = odd ? lo : hi;
    } else {
        const uint32_t h1 = ((uint32_t)(bx + 1) ^ hyz) & HASH_MASK;
        v0 = __ldg(&tab[h0]);
        v1 = __ldg(&tab[h1]);
    }
}

// Main: block = 512 threads = 16 warps. Warp w handles level w for 32
// spatially-adjacent (sorted) points -> coarse-level gathers coalesce.
__global__ void __launch_bounds__(512)
hash_embed_kernel(const float* __restrict__ tables,
                  float2* __restrict__ out,
                  Res16 R)
{
    __shared__ float2 s_out[32][17];   // [point][level], padded row
    __shared__ int    s_idx[32];

    const int warp = threadIdx.x >> 5;   // = level
    const int lane = threadIdx.x & 31;   // = point within block
    const int base = blockIdx.x * 32;

    const float4 pv = g_xs4[base + lane];
    const float px = pv.x, py = pv.y, pz = pv.z;
    if (warp == 0) s_idx[lane] = __float_as_int(pv.w);

    const int level = warp;
    const float res  = R.r[level];
    const float grid = 2.0f / res;   // fp32, matches reference

    // bl = floor((x - BOX_MIN)/grid), BOX_MIN = -1. Bit-exact IEEE path.
    const float fx = (px + 1.0f) / grid;
    const float fy = (py + 1.0f) / grid;
    const float fz = (pz + 1.0f) / grid;
    const float bxf = floorf(fx);
    const float byf = floorf(fy);
    const float bzf = floorf(fz);
    const int bx = (int)bxf;
    const int by = (int)byf;
    const int bz = (int)bzf;

    // Weights: mathematically (x - vmin)/(vmax - vmin) == frac(fx); ~1 ulp
    // from the reference formulation, far under the 1e-3 tolerance.
    const float wx = fx - bxf;
    const float wy = fy - byf;
    const float wz = fz - bzf;

    const uint32_t hy0 = (uint32_t)by * PRIME_Y;
    const uint32_t hy1 = (uint32_t)(by + 1) * PRIME_Y;
    const uint32_t hz0 = (uint32_t)bz * PRIME_Z;
    const uint32_t hz1 = (uint32_t)(bz + 1) * PRIME_Z;

    const float2* __restrict__ tab =
        (const float2*)tables + ((size_t)level << LOG2_HASHMAP_SIZE);

    // 4 (y,z) corner pairs, each fetching both x-corners.
    float2 v000, v100, v001, v101, v010, v110, v011, v111;
    load_xpair(tab, bx, hy0 ^ hz0, v000, v100);
    load_xpair(tab, bx, hy0 ^ hz1, v001, v101);
    load_xpair(tab, bx, hy1 ^ hz0, v010, v110);
    load_xpair(tab, bx, hy1 ^ hz1, v011, v111);

    const float owx = 1.0f - wx;
    const float owy = 1.0f - wy;
    const float owz = 1.0f - wz;

    float2 c00, c01, c10, c11;
    c00.x = v000.x * owx + v100.x * wx;  c00.y = v000.y * owx + v100.y * wx;
    c01.x = v001.x * owx + v101.x * wx;  c01.y = v001.y * owx + v101.y * wx;
    c10.x = v010.x * owx + v110.x * wx;  c10.y = v010.y * owx + v110.y * wx;
    c11.x = v011.x * owx + v111.x * wx;  c11.y = v011.y * owx + v111.y * wx;

    float2 c0, c1;
    c0.x = c00.x * owy + c10.x * wy;  c0.y = c00.y * owy + c10.y * wy;
    c1.x = c01.x * owy + c11.x * wy;  c1.y = c01.y * owy + c11.y * wy;

    float2 r2;
    r2.x = c0.x * owz + c1.x * wz;
    r2.y = c0.y * owz + c1.y * wz;

    s_out[lane][warp] = r2;
    __syncthreads();

    // Coalesced writeback: 16 consecutive threads emit one point's 128B row.
    const int pt  = threadIdx.x >> 4;
    const int lev = threadIdx.x & 15;
    out[(size_t)s_idx[pt] * N_LEVELS + lev] = s_out[pt][lev];
}

extern "C" void kernel_launch(void* const* d_in, const int* in_sizes, int n_in,
                              void* d_out, int out_size)
{
    const float* x      = (const float*)d_in[0];
    const float* tables = (const float*)d_in[1];
    float2* out         = (float2*)d_out;

    // Replicate numpy's RESOLUTIONS computation exactly (double libm, floor).
    Res16 R;
    const double b = exp((log(512.0) - log(16.0)) / 15.0);
    for (int i = 0; i < 16; i++) {
        R.r[i] = (float)floor(16.0 * pow(b, (double)i));
    }

    zero_hist_kernel<<<N_BINS / 1024, 1024>>>();
    hist_kernel<<<N_POINTS / 256, 256>>>(x);
    scan_kernel<<<1, 1024>>>();
    scatter_kernel<<<N_POINTS / 256, 256>>>(x);
    hash_embed_kernel<<<N_POINTS / 32, 512>>>(tables, out, R);
}